// round 16
// baseline (speedup 1.0000x reference)
#include <cuda_runtime.h>
#include <math.h>

// Problem constants: B=32, C=3, H=W=512
#define BB 32
#define CC 3
#define HH 512
#define WW 512
#define PX 4

// Fused kernel, per-batch dual lane mapping (warp-uniform branch):
//  - ROW map  (lanes = 32 consecutive out px, k-stride 32): best when |m01| small
//  - TILE map (lanes = 8x4 out tile, k-stride 8 in x):      best when rotated
// Both paths keep the warp-uniform dead-segment zero-fill and guarded gathers.
__global__ __launch_bounds__(256, 8) void warp_kernel(const float* __restrict__ x,
                                                      const float* __restrict__ thetas,
                                                      const float* __restrict__ l1s,
                                                      const float* __restrict__ l2s,
                                                      float* __restrict__ out) {
    int lane    = threadIdx.x;                        // 0..31
    int ty      = threadIdx.y;                        // 0..7
    int b       = blockIdx.z;
    int px_base = blockIdx.x * 128;                   // CTA: 128 px in x
    int py_base = blockIdx.y * 8;                     // CTA: 8 rows in y

    // theta matrix (translation exactly zero); uniform within the CTA
    float th = -__ldg(thetas + b);
    float c, s;
    __sincosf(th, &s, &c);
    float il1 = 1.0f / __ldg(l1s + b);
    float il2 = 1.0f / __ldg(l2s + b);
    float m00 = c * c * il1 + s * s * il2;
    float m11 = s * s * il1 + c * c * il2;
    float m01 = c * s * (il2 - il1);

    const float* xb = x + (size_t)b * CC * HH * WW;
    const float MARGIN = 1e-3f;

    // grid-constant per-batch mapping choice (uniform everywhere for this b)
    bool use_tile = (24.0f * fabsf(m01) > 3.0f * m11 + 4.0f);

    if (!use_tile) {
        // ================= ROW MAPPING (R13/R15 proven body) =================
        int py  = py_base + ty;
        int px0 = px_base + lane;
        float Y = ((float)py + 0.5f) * (2.0f / (float)HH) - 1.0f;

        {   // warp-uniform dead-segment test (x endpoints)
            float Xlo = ((float)px_base + 0.5f)   * (2.0f / WW) - 1.0f;
            float Xhi = ((float)px_base + 127.5f) * (2.0f / WW) - 1.0f;
            float gx_lo = (m00 * Xlo + m01 * Y + 1.0f) * (WW * 0.5f) - 0.5f;
            float gx_hi = (m00 * Xhi + m01 * Y + 1.0f) * (WW * 0.5f) - 0.5f;
            float gyA   = (m01 * Xlo + m11 * Y + 1.0f) * (HH * 0.5f) - 0.5f;
            float gyB   = (m01 * Xhi + m11 * Y + 1.0f) * (HH * 0.5f) - 0.5f;
            float gy_lo = fminf(gyA, gyB), gy_hi = fmaxf(gyA, gyB);
            bool dead = (gx_hi < -1.0f - MARGIN) | (gx_lo >= (float)WW + MARGIN) |
                        (gy_hi < -1.0f - MARGIN) | (gy_lo >= (float)HH + MARGIN);
            if (dead) {
                float4 z = make_float4(0.f, 0.f, 0.f, 0.f);
                float4* dst = (float4*)(out + ((size_t)b * CC) * HH * WW +
                                        (size_t)py * WW + px_base) + lane;
#pragma unroll
                for (int cc = 0; cc < CC; cc++)
                    __stcs(dst + cc * (HH * WW / 4), z);
                return;
            }
        }

        float X  = ((float)px0 + 0.5f) * (2.0f / (float)WW) - 1.0f;
        float gx = (m00 * X + m01 * Y + 1.0f) * ((float)WW * 0.5f) - 0.5f;
        float gy = (m01 * X + m11 * Y + 1.0f) * ((float)HH * 0.5f) - 0.5f;
        float sx = 32.0f * m00;
        float sy = 32.0f * m01;

        float w00[PX], w01[PX], w10[PX], w11[PX];
        int   i00[PX];
#pragma unroll
        for (int k = 0; k < PX; k++) {
            float x0f = floorf(gx), y0f = floorf(gy);
            int x0 = (int)x0f, y0 = (int)y0f;
            float wx1 = gx - x0f, wx0 = 1.0f - wx1;
            float wy1 = gy - y0f, wy0 = 1.0f - wy1;
            float cx0 = ((unsigned)x0       < (unsigned)WW) ? wx0 : 0.0f;
            float cx1 = ((unsigned)(x0 + 1) < (unsigned)WW) ? wx1 : 0.0f;
            float cy0 = ((unsigned)y0       < (unsigned)HH) ? wy0 : 0.0f;
            float cy1 = ((unsigned)(y0 + 1) < (unsigned)HH) ? wy1 : 0.0f;
            w00[k] = cy0 * cx0;  w01[k] = cy0 * cx1;
            w10[k] = cy1 * cx0;  w11[k] = cy1 * cx1;
            i00[k] = y0 * WW + x0;
            gx += sx; gy += sy;
        }

        float* ob = out + ((size_t)b * CC) * HH * WW + (size_t)py * WW + px0;
#pragma unroll
        for (int cc = 0; cc < CC; cc++) {
            const float* p = xb + (size_t)cc * HH * WW;
            float v[PX];
#pragma unroll
            for (int k = 0; k < PX; k++) {
                int i0 = i00[k];
                float acc = 0.0f;
                if (w00[k] != 0.0f) acc += w00[k] * __ldg(p + i0);
                if (w01[k] != 0.0f) acc += w01[k] * __ldg(p + i0 + 1);
                if (w10[k] != 0.0f) acc += w10[k] * __ldg(p + i0 + WW);
                if (w11[k] != 0.0f) acc += w11[k] * __ldg(p + i0 + WW + 1);
                v[k] = acc;
            }
            float* oc = ob + (size_t)cc * HH * WW;
#pragma unroll
            for (int k = 0; k < PX; k++)
                __stcs(oc + 32 * k, v[k]);
        }
    } else {
        // ================= TILE MAPPING (8x4 lanes per warp) =================
        // warp w covers x:[pxw, pxw+32), y:[pyw, pyw+4)
        int pxw = px_base + 32 * (ty & 3);
        int pyw = py_base + 4 * (ty >> 2);
        int i_l = lane & 7;          // 0..7  (x within tile)
        int j_l = lane >> 3;         // 0..3  (y within tile)
        int py  = pyw + j_l;
        int px0 = pxw + i_l;         // +8k per step

        {   // warp-uniform dead-region test (4 extreme corners, affine map)
            float Xlo = ((float)pxw + 0.5f)  * (2.0f / WW) - 1.0f;
            float Xhi = ((float)pxw + 31.5f) * (2.0f / WW) - 1.0f;
            float Ylo = ((float)pyw + 0.5f)  * (2.0f / HH) - 1.0f;
            float Yhi = ((float)pyw + 3.5f)  * (2.0f / HH) - 1.0f;
            float ax_lo = fminf(m01 * Ylo, m01 * Yhi);
            float ax_hi = fmaxf(m01 * Ylo, m01 * Yhi);
            float gx_lo = (m00 * Xlo + ax_lo + 1.0f) * (WW * 0.5f) - 0.5f;
            float gx_hi = (m00 * Xhi + ax_hi + 1.0f) * (WW * 0.5f) - 0.5f;
            float ay_lo = fminf(m01 * Xlo, m01 * Xhi);
            float ay_hi = fmaxf(m01 * Xlo, m01 * Xhi);
            float gy_lo = (m11 * Ylo + ay_lo + 1.0f) * (HH * 0.5f) - 0.5f;
            float gy_hi = (m11 * Yhi + ay_hi + 1.0f) * (HH * 0.5f) - 0.5f;
            bool dead = (gx_hi < -1.0f - MARGIN) | (gx_lo >= (float)WW + MARGIN) |
                        (gy_hi < -1.0f - MARGIN) | (gy_lo >= (float)HH + MARGIN);
            if (dead) {
                // 32px x 4 rows x 3ch zeros: lane -> (row = lane>>3, quad = lane&7)
                float4 z = make_float4(0.f, 0.f, 0.f, 0.f);
                float4* dst = (float4*)(out + ((size_t)b * CC) * HH * WW +
                                        (size_t)(pyw + j_l) * WW + pxw) + i_l;
#pragma unroll
                for (int cc = 0; cc < CC; cc++)
                    __stcs(dst + cc * (HH * WW / 4), z);
                return;
            }
        }

        float X  = ((float)px0 + 0.5f) * (2.0f / (float)WW) - 1.0f;
        float Y  = ((float)py  + 0.5f) * (2.0f / (float)HH) - 1.0f;
        float gx = (m00 * X + m01 * Y + 1.0f) * ((float)WW * 0.5f) - 0.5f;
        float gy = (m01 * X + m11 * Y + 1.0f) * ((float)HH * 0.5f) - 0.5f;
        float sx = 8.0f * m00;
        float sy = 8.0f * m01;

        float w00[PX], w01[PX], w10[PX], w11[PX];
        int   i00[PX];
#pragma unroll
        for (int k = 0; k < PX; k++) {
            float x0f = floorf(gx), y0f = floorf(gy);
            int x0 = (int)x0f, y0 = (int)y0f;
            float wx1 = gx - x0f, wx0 = 1.0f - wx1;
            float wy1 = gy - y0f, wy0 = 1.0f - wy1;
            float cx0 = ((unsigned)x0       < (unsigned)WW) ? wx0 : 0.0f;
            float cx1 = ((unsigned)(x0 + 1) < (unsigned)WW) ? wx1 : 0.0f;
            float cy0 = ((unsigned)y0       < (unsigned)HH) ? wy0 : 0.0f;
            float cy1 = ((unsigned)(y0 + 1) < (unsigned)HH) ? wy1 : 0.0f;
            w00[k] = cy0 * cx0;  w01[k] = cy0 * cx1;
            w10[k] = cy1 * cx0;  w11[k] = cy1 * cx1;
            i00[k] = y0 * WW + x0;
            gx += sx; gy += sy;
        }

        float* ob = out + ((size_t)b * CC) * HH * WW + (size_t)py * WW + px0;
#pragma unroll
        for (int cc = 0; cc < CC; cc++) {
            const float* p = xb + (size_t)cc * HH * WW;
            float v[PX];
#pragma unroll
            for (int k = 0; k < PX; k++) {
                int i0 = i00[k];
                float acc = 0.0f;
                if (w00[k] != 0.0f) acc += w00[k] * __ldg(p + i0);
                if (w01[k] != 0.0f) acc += w01[k] * __ldg(p + i0 + 1);
                if (w10[k] != 0.0f) acc += w10[k] * __ldg(p + i0 + WW);
                if (w11[k] != 0.0f) acc += w11[k] * __ldg(p + i0 + WW + 1);
                v[k] = acc;
            }
            float* oc = ob + (size_t)cc * HH * WW;
#pragma unroll
            for (int k = 0; k < PX; k++)
                __stcs(oc + 8 * k, v[k]);
        }
    }
}

extern "C" void kernel_launch(void* const* d_in, const int* in_sizes, int n_in,
                              void* d_out, int out_size) {
    const float* x      = (const float*)d_in[0];
    const float* thetas = (const float*)d_in[1];
    const float* l1s    = (const float*)d_in[2];
    const float* l2s    = (const float*)d_in[3];
    float* out = (float*)d_out;

    dim3 block(32, 8, 1);
    dim3 grid(4, 64, BB);   // 128 px x 8 rows per CTA
    warp_kernel<<<grid, block>>>(x, thetas, l1s, l2s, out);
}